// round 2
// baseline (speedup 1.0000x reference)
#include <cuda_runtime.h>
#include <math.h>

// Problem constants
#define NN 100000
#define NE 1600000
#define IN_DIM 128

static constexpr int SCAN_BLK = 1024;
static constexpr int NB1 = (NN + SCAN_BLK - 1) / SCAN_BLK; // 98

// ---------------- scratch (static device allocations) ----------------
__device__ float g_h[(size_t)NN * 256];   // GEMM output (per layer)
__device__ float g_x[(size_t)NN * 256];   // aggregated + ELU output (next layer input)
__device__ float g_as[NN * 4];            // alpha_src per node per head
__device__ float g_ad[NN * 4];            // alpha_dst per node per head
__device__ float g_inv[NN * 4];           // 1/(denom+eps) per node per head
__device__ float g_att[(size_t)NE * 4];   // exp(e - max) per sorted edge per head
__device__ int   g_cnt[NN];               // in-degree
__device__ int   g_cur[NN];               // scatter cursor
__device__ int   g_row[NN + 1];           // CSR row offsets (by dst)
__device__ int   g_srcs[NE];              // src node id per sorted edge
__device__ int   g_bsum[NB1];             // scan block sums

// ---------------- CSR construction ----------------
__global__ void zero_k() {
    int i = blockIdx.x * blockDim.x + threadIdx.x;
    if (i < NN) { g_cnt[i] = 0; g_cur[i] = 0; }
}

__global__ void deg_k(const int* __restrict__ dst) {
    int e = blockIdx.x * blockDim.x + threadIdx.x;
    if (e < NE) atomicAdd(&g_cnt[dst[e]], 1);
}

__global__ void scan1_k() {
    __shared__ int s[SCAN_BLK];
    int i = blockIdx.x * SCAN_BLK + threadIdx.x;
    int v = (i < NN) ? g_cnt[i] : 0;
    s[threadIdx.x] = v;
    __syncthreads();
    for (int off = 1; off < SCAN_BLK; off <<= 1) {
        int t = (threadIdx.x >= off) ? s[threadIdx.x - off] : 0;
        __syncthreads();
        s[threadIdx.x] += t;
        __syncthreads();
    }
    if (i < NN) g_row[i] = s[threadIdx.x] - v;   // exclusive, block-local
    if (threadIdx.x == SCAN_BLK - 1) g_bsum[blockIdx.x] = s[threadIdx.x];
}

__global__ void scan2_k() {
    if (threadIdx.x == 0) {
        int run = 0;
        for (int b = 0; b < NB1; b++) { int t = g_bsum[b]; g_bsum[b] = run; run += t; }
    }
}

__global__ void scan3_k() {
    int i = blockIdx.x * blockDim.x + threadIdx.x;
    if (i < NN) g_row[i] += g_bsum[i / SCAN_BLK];
    if (i == 0) g_row[NN] = NE;
}

__global__ void scatter_k(const int* __restrict__ src, const int* __restrict__ dst) {
    int e = blockIdx.x * blockDim.x + threadIdx.x;
    if (e >= NE) return;
    int d = dst[e];
    int pos = g_row[d] + atomicAdd(&g_cur[d], 1);
    g_srcs[pos] = src[e];
}

// ---------------- GEMM: C[M,Nc] = A[M,K] @ W[K,Nc] (fp32, 64x64x16 tiles) ----------------
__global__ void gemm_k(const float* __restrict__ Ain, int use_gx,
                       const float* __restrict__ W,
                       int M, int K, int Nc) {
    const float* A = use_gx ? g_x : Ain;
    __shared__ float sA[16][68];   // [k][m], padded for float4-aligned rows
    __shared__ float sB[16][64];   // [k][n]
    int m0 = blockIdx.x * 64, n0 = blockIdx.y * 64;
    int tid = threadIdx.x;
    int ty = tid >> 4, tx = tid & 15;

    float acc[4][4];
#pragma unroll
    for (int i = 0; i < 4; i++)
#pragma unroll
        for (int j = 0; j < 4; j++) acc[i][j] = 0.0f;

    for (int k0 = 0; k0 < K; k0 += 16) {
        {   // load A tile: thread -> (m = tid/4, 4 consecutive k)
            int m = tid >> 2, kq = tid & 3;
            int row = m0 + m;
            float4 v = (row < M) ? *(const float4*)(A + (size_t)row * K + k0 + kq * 4)
                                 : make_float4(0.f, 0.f, 0.f, 0.f);
            sA[kq * 4 + 0][m] = v.x;
            sA[kq * 4 + 1][m] = v.y;
            sA[kq * 4 + 2][m] = v.z;
            sA[kq * 4 + 3][m] = v.w;
        }
        {   // load B tile: thread -> (k = tid/16, 4 consecutive n)
            int k = tid >> 4, nq = tid & 15;
            float4 v = *(const float4*)(W + (size_t)(k0 + k) * Nc + n0 + nq * 4);
            *(float4*)&sB[k][nq * 4] = v;
        }
        __syncthreads();
#pragma unroll
        for (int k = 0; k < 16; k++) {
            float4 a4 = *(const float4*)&sA[k][ty * 4];
            float4 b4 = *(const float4*)&sB[k][tx * 4];
            float a[4] = {a4.x, a4.y, a4.z, a4.w};
            float b[4] = {b4.x, b4.y, b4.z, b4.w};
#pragma unroll
            for (int i = 0; i < 4; i++)
#pragma unroll
                for (int j = 0; j < 4; j++)
                    acc[i][j] = fmaf(a[i], b[j], acc[i][j]);
        }
        __syncthreads();
    }
#pragma unroll
    for (int i = 0; i < 4; i++) {
        int row = m0 + ty * 4 + i;
        if (row < M)
            *(float4*)(g_h + (size_t)row * Nc + n0 + tx * 4) =
                make_float4(acc[i][0], acc[i][1], acc[i][2], acc[i][3]);
    }
}

// ---------------- alpha_s / alpha_d per node (warp per node) ----------------
__global__ void alpha_k(const float* __restrict__ avec, int heads, int dim) {
    int warp = (blockIdx.x * blockDim.x + threadIdx.x) >> 5;
    int lane = threadIdx.x & 31;
    if (warp >= NN) return;
    const float* hr = g_h + (size_t)warp * heads * dim;
    for (int hd = 0; hd < heads; hd++) {
        float s = 0.f, dd = 0.f;
        for (int i = lane; i < dim; i += 32) {
            float v = hr[hd * dim + i];
            s  = fmaf(v, avec[hd * 2 * dim + i], s);
            dd = fmaf(v, avec[hd * 2 * dim + dim + i], dd);
        }
#pragma unroll
        for (int off = 16; off; off >>= 1) {
            s  += __shfl_xor_sync(0xffffffffu, s, off);
            dd += __shfl_xor_sync(0xffffffffu, dd, off);
        }
        if (lane == 0) {
            g_as[warp * heads + hd] = s;
            g_ad[warp * heads + hd] = dd;
        }
    }
}

// ---------------- attention softmax (warp per dst node, no atomics) ----------------
template <int H>
__global__ void attn_k() {
    int node = (blockIdx.x * blockDim.x + threadIdx.x) >> 5;
    int lane = threadIdx.x & 31;
    if (node >= NN) return;
    int beg = g_row[node], end = g_row[node + 1];

    float ad[H];
#pragma unroll
    for (int h = 0; h < H; h++) ad[h] = g_ad[node * H + h];

    float m[H];
#pragma unroll
    for (int h = 0; h < H; h++) m[h] = -1e30f;

    for (int i = beg + lane; i < end; i += 32) {
        int sv = g_srcs[i];
#pragma unroll
        for (int h = 0; h < H; h++) {
            float e = g_as[sv * H + h] + ad[h];
            e = (e > 0.f) ? e : 0.2f * e;
            m[h] = fmaxf(m[h], e);
        }
    }
#pragma unroll
    for (int h = 0; h < H; h++)
#pragma unroll
        for (int off = 16; off; off >>= 1)
            m[h] = fmaxf(m[h], __shfl_xor_sync(0xffffffffu, m[h], off));

    float sum[H];
#pragma unroll
    for (int h = 0; h < H; h++) sum[h] = 0.f;

    for (int i = beg + lane; i < end; i += 32) {
        int sv = g_srcs[i];
#pragma unroll
        for (int h = 0; h < H; h++) {
            float e = g_as[sv * H + h] + ad[h];
            e = (e > 0.f) ? e : 0.2f * e;
            float ex = __expf(e - m[h]);
            sum[h] += ex;
            g_att[(size_t)i * H + h] = ex;
        }
    }
#pragma unroll
    for (int h = 0; h < H; h++)
#pragma unroll
        for (int off = 16; off; off >>= 1)
            sum[h] += __shfl_xor_sync(0xffffffffu, sum[h], off);

    if (lane == 0) {
#pragma unroll
        for (int h = 0; h < H; h++)
            g_inv[node * H + h] = 1.0f / (sum[h] + 1e-16f);
    }
}

// ---------------- message aggregation (warp per (node, head), no atomics) ----------------
template <int H, bool DO_ELU>
__global__ void agg_k(float* __restrict__ outp, int use_gx) {
    int gw = (blockIdx.x * blockDim.x + threadIdx.x) >> 5;
    int lane = threadIdx.x & 31;
    if (gw >= NN * H) return;
    int node = gw / H;
    int head = gw - node * H;
    int beg = g_row[node], end = g_row[node + 1];
    float inv = g_inv[node * H + head];

    float ax = 0.f, ay = 0.f;
    for (int i = beg; i < end; i++) {
        int sv = g_srcs[i];
        float a = g_att[(size_t)i * H + head] * inv;
        const float2 hv = *(const float2*)(g_h + (size_t)sv * (H * 64) + head * 64 + lane * 2);
        ax = fmaf(hv.x, a, ax);
        ay = fmaf(hv.y, a, ay);
    }
    if (DO_ELU) {
        ax = (ax > 0.f) ? ax : expm1f(ax);
        ay = (ay > 0.f) ? ay : expm1f(ay);
    }
    float* out = use_gx ? g_x : outp;
    *(float2*)(out + (size_t)node * (H * 64) + head * 64 + lane * 2) = make_float2(ax, ay);
}

// ---------------- launch ----------------
extern "C" void kernel_launch(void* const* d_in, const int* in_sizes, int n_in,
                              void* d_out, int out_size) {
    const float* x  = (const float*)d_in[0];
    const int*   ei = (const int*)d_in[1];
    const int*   src = ei;
    const int*   dst = ei + NE;
    const float* W0 = (const float*)d_in[2];
    const float* a0 = (const float*)d_in[3];
    const float* W1 = (const float*)d_in[4];
    const float* a1 = (const float*)d_in[5];
    const float* W2 = (const float*)d_in[6];
    const float* a2 = (const float*)d_in[7];
    float* out = (float*)d_out;

    // --- CSR by dst (counting sort) ---
    zero_k<<<(NN + 255) / 256, 256>>>();
    deg_k<<<(NE + 255) / 256, 256>>>(dst);
    scan1_k<<<NB1, SCAN_BLK>>>();
    scan2_k<<<1, 32>>>();
    scan3_k<<<(NN + 255) / 256, 256>>>();
    scatter_k<<<(NE + 255) / 256, 256>>>(src, dst);

    dim3 gemm_blk(256);
    int node_warp_blocks = (NN + 3) / 4;        // 4 warps / 128-thread block
    int agg4_blocks = (NN * 4 + 3) / 4;

    // --- Layer 0: x[N,128] -> h[N,4,64], concat, ELU ---
    gemm_k<<<dim3((NN + 63) / 64, 256 / 64), gemm_blk>>>(x, 0, W0, NN, IN_DIM, 256);
    alpha_k<<<node_warp_blocks, 128>>>(a0, 4, 64);
    attn_k<4><<<node_warp_blocks, 128>>>();
    agg_k<4, true><<<agg4_blocks, 128>>>(nullptr, 1);   // writes g_x (with ELU)

    // --- Layer 1: g_x[N,256] -> h[N,4,64], concat, ELU ---
    gemm_k<<<dim3((NN + 63) / 64, 256 / 64), gemm_blk>>>(nullptr, 1, W1, NN, 256, 256);
    alpha_k<<<node_warp_blocks, 128>>>(a1, 4, 64);
    attn_k<4><<<node_warp_blocks, 128>>>();
    agg_k<4, true><<<agg4_blocks, 128>>>(nullptr, 1);   // writes g_x (with ELU)

    // --- Layer 2: g_x[N,256] -> h[N,1,64], mean over 1 head == identity ---
    gemm_k<<<dim3((NN + 63) / 64, 64 / 64), gemm_blk>>>(nullptr, 1, W2, NN, 256, 64);
    alpha_k<<<node_warp_blocks, 128>>>(a2, 1, 64);
    attn_k<1><<<node_warp_blocks, 128>>>();
    agg_k<1, false><<<node_warp_blocks, 128>>>(out, 0); // writes d_out directly
}

// round 7
// speedup vs baseline: 1.0880x; 1.0880x over previous
#include <cuda_runtime.h>
#include <math.h>

// Problem constants
#define NN 100000
#define NE 1600000
#define IN_DIM 128

static constexpr int SCAN_BLK = 1024;
static constexpr int NB1 = (NN + SCAN_BLK - 1) / SCAN_BLK; // 98

// ---------------- scratch (static device allocations) ----------------
__device__ float g_h[(size_t)NN * 256];   // GEMM output (per layer)
__device__ float g_x[(size_t)NN * 256];   // aggregated + ELU output (next layer input)
__device__ float g_as[NN * 4];            // alpha_src per node per head
__device__ float g_ad[NN * 4];            // alpha_dst per node per head
__device__ float g_inv[NN * 4];           // 1/(denom+eps) per node per head
__device__ float g_att[(size_t)NE * 4];   // exp(e - max) per sorted edge per head
__device__ int   g_cnt[NN];               // in-degree
__device__ int   g_cur[NN];               // scatter cursor
__device__ int   g_row[NN + 1];           // CSR row offsets (by dst)
__device__ int   g_srcs[NE];              // src node id per sorted edge
__device__ int   g_bsum[NB1];             // scan block sums

// ---------------- CSR construction ----------------
__global__ void zero_k() {
    int i = blockIdx.x * blockDim.x + threadIdx.x;
    if (i < NN) { g_cnt[i] = 0; g_cur[i] = 0; }
}

__global__ void deg_k(const int* __restrict__ dst) {
    int e = blockIdx.x * blockDim.x + threadIdx.x;
    if (e < NE) atomicAdd(&g_cnt[dst[e]], 1);
}

__global__ void scan1_k() {
    __shared__ int s[SCAN_BLK];
    int i = blockIdx.x * SCAN_BLK + threadIdx.x;
    int v = (i < NN) ? g_cnt[i] : 0;
    s[threadIdx.x] = v;
    __syncthreads();
    for (int off = 1; off < SCAN_BLK; off <<= 1) {
        int t = (threadIdx.x >= off) ? s[threadIdx.x - off] : 0;
        __syncthreads();
        s[threadIdx.x] += t;
        __syncthreads();
    }
    if (i < NN) g_row[i] = s[threadIdx.x] - v;   // exclusive, block-local
    if (threadIdx.x == SCAN_BLK - 1) g_bsum[blockIdx.x] = s[threadIdx.x];
}

__global__ void scan2_k() {
    if (threadIdx.x == 0) {
        int run = 0;
        for (int b = 0; b < NB1; b++) { int t = g_bsum[b]; g_bsum[b] = run; run += t; }
    }
}

__global__ void scan3_k() {
    int i = blockIdx.x * blockDim.x + threadIdx.x;
    if (i < NN) g_row[i] += g_bsum[i / SCAN_BLK];
    if (i == 0) g_row[NN] = NE;
}

__global__ void scatter_k(const int* __restrict__ src, const int* __restrict__ dst) {
    int e = blockIdx.x * blockDim.x + threadIdx.x;
    if (e >= NE) return;
    int d = dst[e];
    int pos = g_row[d] + atomicAdd(&g_cur[d], 1);
    g_srcs[pos] = src[e];
}

// ---------------- GEMM: C[M,Nc] = A[M,K] @ W[K,Nc] ----------------
// 128 x BN tile, BK=16, 256 threads, per-thread 8 x TN microkernel.
template <int BN, int TN>
__global__ __launch_bounds__(256) void gemm_k(const float* __restrict__ Ain, int use_gx,
                                              const float* __restrict__ W,
                                              int M, int K, int Nc) {
    constexpr int BM = 128, BK = 16;
    const float* A = use_gx ? g_x : Ain;
    __shared__ float sA[BK][BM + 4];
    __shared__ float sB[BK][BN];

    int tid = threadIdx.x;
    int m0 = blockIdx.x * BM, n0 = blockIdx.y * BN;
    int tx = tid & 15, ty = tid >> 4;              // tx: 16 col groups, ty: 16 row groups

    // A global load mapping: 2 threads per row, each 2 float4 (8 k-values)
    int ar = tid >> 1;
    int ak = (tid & 1) * 8;
    // B global load mapping
    int brow = tid >> 4;
    int bcol = (tid & 15) * (BN / 16);

    float acc[8][TN];
#pragma unroll
    for (int i = 0; i < 8; i++)
#pragma unroll
        for (int j = 0; j < TN; j++) acc[i][j] = 0.0f;

    for (int k0 = 0; k0 < K; k0 += BK) {
        // global -> regs
        float4 av0, av1;
        bool rowok = (m0 + ar) < M;
        const float* Arow = A + (size_t)(m0 + ar) * K + k0 + ak;
        av0 = rowok ? *(const float4*)(Arow)     : make_float4(0.f, 0.f, 0.f, 0.f);
        av1 = rowok ? *(const float4*)(Arow + 4) : make_float4(0.f, 0.f, 0.f, 0.f);
        float4 bv0, bv1;
        const float* Wrow = W + (size_t)(k0 + brow) * Nc + n0 + bcol;
        bv0 = *(const float4*)(Wrow);
        if (BN == 128) bv1 = *(const float4*)(Wrow + 4);

        __syncthreads();  // previous chunk's compute done
        // regs -> smem (A transposed)
        sA[ak + 0][ar] = av0.x; sA[ak + 1][ar] = av0.y;
        sA[ak + 2][ar] = av0.z; sA[ak + 3][ar] = av0.w;
        sA[ak + 4][ar] = av1.x; sA[ak + 5][ar] = av1.y;
        sA[ak + 6][ar] = av1.z; sA[ak + 7][ar] = av1.w;
        *(float4*)&sB[brow][bcol] = bv0;
        if (BN == 128) *(float4*)&sB[brow][bcol + 4] = bv1;
        __syncthreads();

#pragma unroll
        for (int k = 0; k < BK; k++) {
            float a[8];
            *(float4*)&a[0] = *(const float4*)&sA[k][ty * 8];
            *(float4*)&a[4] = *(const float4*)&sA[k][ty * 8 + 4];
            float b[TN];
#pragma unroll
            for (int j = 0; j < TN; j += 4)
                *(float4*)&b[j] = *(const float4*)&sB[k][tx * TN + j];
#pragma unroll
            for (int i = 0; i < 8; i++)
#pragma unroll
                for (int j = 0; j < TN; j++)
                    acc[i][j] = fmaf(a[i], b[j], acc[i][j]);
        }
    }

#pragma unroll
    for (int i = 0; i < 8; i++) {
        int row = m0 + ty * 8 + i;
        if (row < M) {
            float* Crow = g_h + (size_t)row * Nc + n0 + tx * TN;
#pragma unroll
            for (int j = 0; j < TN; j += 4)
                *(float4*)(Crow + j) = make_float4(acc[i][j], acc[i][j + 1], acc[i][j + 2], acc[i][j + 3]);
        }
    }
}

// ---------------- alpha_s / alpha_d per node (warp per node) ----------------
__global__ void alpha_k(const float* __restrict__ avec, int heads, int dim) {
    int warp = (blockIdx.x * blockDim.x + threadIdx.x) >> 5;
    int lane = threadIdx.x & 31;
    if (warp >= NN) return;
    const float* hr = g_h + (size_t)warp * heads * dim;
    for (int hd = 0; hd < heads; hd++) {
        float s = 0.f, dd = 0.f;
        for (int i = lane; i < dim; i += 32) {
            float v = hr[hd * dim + i];
            s  = fmaf(v, avec[hd * 2 * dim + i], s);
            dd = fmaf(v, avec[hd * 2 * dim + dim + i], dd);
        }
#pragma unroll
        for (int off = 16; off; off >>= 1) {
            s  += __shfl_xor_sync(0xffffffffu, s, off);
            dd += __shfl_xor_sync(0xffffffffu, dd, off);
        }
        if (lane == 0) {
            g_as[warp * heads + hd] = s;
            g_ad[warp * heads + hd] = dd;
        }
    }
}

// ---------------- attention softmax (warp per dst node, no atomics) ----------------
template <int H>
__global__ void attn_k() {
    int node = (blockIdx.x * blockDim.x + threadIdx.x) >> 5;
    int lane = threadIdx.x & 31;
    if (node >= NN) return;
    int beg = g_row[node], end = g_row[node + 1];

    float ad[H];
#pragma unroll
    for (int h = 0; h < H; h++) ad[h] = g_ad[node * H + h];

    float m[H];
#pragma unroll
    for (int h = 0; h < H; h++) m[h] = -1e30f;

    for (int i = beg + lane; i < end; i += 32) {
        int sv = g_srcs[i];
#pragma unroll
        for (int h = 0; h < H; h++) {
            float e = g_as[sv * H + h] + ad[h];
            e = (e > 0.f) ? e : 0.2f * e;
            m[h] = fmaxf(m[h], e);
        }
    }
#pragma unroll
    for (int h = 0; h < H; h++)
#pragma unroll
        for (int off = 16; off; off >>= 1)
            m[h] = fmaxf(m[h], __shfl_xor_sync(0xffffffffu, m[h], off));

    float sum[H];
#pragma unroll
    for (int h = 0; h < H; h++) sum[h] = 0.f;

    for (int i = beg + lane; i < end; i += 32) {
        int sv = g_srcs[i];
#pragma unroll
        for (int h = 0; h < H; h++) {
            float e = g_as[sv * H + h] + ad[h];
            e = (e > 0.f) ? e : 0.2f * e;
            float ex = __expf(e - m[h]);
            sum[h] += ex;
            g_att[(size_t)i * H + h] = ex;
        }
    }
#pragma unroll
    for (int h = 0; h < H; h++)
#pragma unroll
        for (int off = 16; off; off >>= 1)
            sum[h] += __shfl_xor_sync(0xffffffffu, sum[h], off);

    if (lane == 0) {
#pragma unroll
        for (int h = 0; h < H; h++)
            g_inv[node * H + h] = 1.0f / (sum[h] + 1e-16f);
    }
}

// ---------------- aggregation, H=4: warp per node, all heads; writes g_x with ELU ----
__global__ void agg4_k() {
    int node = (blockIdx.x * blockDim.x + threadIdx.x) >> 5;
    int lane = threadIdx.x & 31;
    if (node >= NN) return;
    int beg = g_row[node], end = g_row[node + 1];
    int hd = lane >> 3;                       // 8 lanes per head (8 floats each)
    float inv = g_inv[node * 4 + hd];

    float4 acc0 = make_float4(0.f, 0.f, 0.f, 0.f);
    float4 acc1 = make_float4(0.f, 0.f, 0.f, 0.f);

    int sv = (beg < end) ? g_srcs[beg] : 0;
    for (int i = beg; i < end; i++) {
        int svn = (i + 1 < end) ? g_srcs[i + 1] : 0;
        float a = g_att[(size_t)i * 4 + hd] * inv;
        const float* hr = g_h + (size_t)sv * 256 + lane * 8;
        float4 v0 = *(const float4*)(hr);
        float4 v1 = *(const float4*)(hr + 4);
        acc0.x = fmaf(v0.x, a, acc0.x); acc0.y = fmaf(v0.y, a, acc0.y);
        acc0.z = fmaf(v0.z, a, acc0.z); acc0.w = fmaf(v0.w, a, acc0.w);
        acc1.x = fmaf(v1.x, a, acc1.x); acc1.y = fmaf(v1.y, a, acc1.y);
        acc1.z = fmaf(v1.z, a, acc1.z); acc1.w = fmaf(v1.w, a, acc1.w);
        sv = svn;
    }
    // ELU
    acc0.x = (acc0.x > 0.f) ? acc0.x : expm1f(acc0.x);
    acc0.y = (acc0.y > 0.f) ? acc0.y : expm1f(acc0.y);
    acc0.z = (acc0.z > 0.f) ? acc0.z : expm1f(acc0.z);
    acc0.w = (acc0.w > 0.f) ? acc0.w : expm1f(acc0.w);
    acc1.x = (acc1.x > 0.f) ? acc1.x : expm1f(acc1.x);
    acc1.y = (acc1.y > 0.f) ? acc1.y : expm1f(acc1.y);
    acc1.z = (acc1.z > 0.f) ? acc1.z : expm1f(acc1.z);
    acc1.w = (acc1.w > 0.f) ? acc1.w : expm1f(acc1.w);

    float* out = g_x + (size_t)node * 256 + lane * 8;
    *(float4*)(out)     = acc0;
    *(float4*)(out + 4) = acc1;
}

// ---------------- aggregation, H=1 (final layer, writes d_out, no ELU) ----------------
__global__ void agg1_k(float* __restrict__ outp) {
    int node = (blockIdx.x * blockDim.x + threadIdx.x) >> 5;
    int lane = threadIdx.x & 31;
    if (node >= NN) return;
    int beg = g_row[node], end = g_row[node + 1];
    float inv = g_inv[node];

    float ax = 0.f, ay = 0.f;
    int sv = (beg < end) ? g_srcs[beg] : 0;
    for (int i = beg; i < end; i++) {
        int svn = (i + 1 < end) ? g_srcs[i + 1] : 0;
        float a = g_att[i] * inv;
        const float2 hv = *(const float2*)(g_h + (size_t)sv * 64 + lane * 2);
        ax = fmaf(hv.x, a, ax);
        ay = fmaf(hv.y, a, ay);
        sv = svn;
    }
    *(float2*)(outp + (size_t)node * 64 + lane * 2) = make_float2(ax, ay);
}

// ---------------- launch ----------------
extern "C" void kernel_launch(void* const* d_in, const int* in_sizes, int n_in,
                              void* d_out, int out_size) {
    const float* x  = (const float*)d_in[0];
    const int*   ei = (const int*)d_in[1];
    const int*   src = ei;
    const int*   dst = ei + NE;
    const float* W0 = (const float*)d_in[2];
    const float* a0 = (const float*)d_in[3];
    const float* W1 = (const float*)d_in[4];
    const float* a1 = (const float*)d_in[5];
    const float* W2 = (const float*)d_in[6];
    const float* a2 = (const float*)d_in[7];
    float* out = (float*)d_out;

    int node_warp_blocks = (NN + 3) / 4;        // 4 warps / 128-thread block
    dim3 g0((NN + 127) / 128, 2), g1((NN + 127) / 128, 2), g2((NN + 127) / 128, 1);

    // --- CSR by dst (counting sort), launches 0-4 ---
    zero_k<<<(NN + 255) / 256, 256>>>();
    deg_k<<<(NE + 255) / 256, 256>>>(dst);
    scan1_k<<<NB1, SCAN_BLK>>>();
    scan2_k<<<1, 32>>>();
    scan3_k<<<(NN + 255) / 256, 256>>>();

    // --- Layer 0 GEMM at launch index 5 (ncu -s 5 profiles this) ---
    gemm_k<128, 8><<<g0, 256>>>(x, 0, W0, NN, IN_DIM, 256);

    scatter_k<<<(NE + 255) / 256, 256>>>(src, dst);

    // --- Layer 0 edge phase ---
    alpha_k<<<node_warp_blocks, 128>>>(a0, 4, 64);
    attn_k<4><<<node_warp_blocks, 128>>>();
    agg4_k<<<node_warp_blocks, 128>>>();

    // --- Layer 1 ---
    gemm_k<128, 8><<<g1, 256>>>(nullptr, 1, W1, NN, 256, 256);
    alpha_k<<<node_warp_blocks, 128>>>(a1, 4, 64);
    attn_k<4><<<node_warp_blocks, 128>>>();
    agg4_k<<<node_warp_blocks, 128>>>();

    // --- Layer 2 ---
    gemm_k<64, 4><<<g2, 256>>>(nullptr, 1, W2, NN, 256, 64);
    alpha_k<<<node_warp_blocks, 128>>>(a2, 1, 64);
    attn_k<1><<<node_warp_blocks, 128>>>();
    agg1_k<<<node_warp_blocks, 128>>>(out);
}

// round 12
// speedup vs baseline: 1.4581x; 1.3401x over previous
#include <cuda_runtime.h>
#include <cuda_bf16.h>
#include <math.h>
#include <stdint.h>

// Problem constants
#define NN 100000
#define NE 1600000
#define IN_DIM 128

static constexpr int SCAN_BLK = 1024;
static constexpr int NB1 = (NN + SCAN_BLK - 1) / SCAN_BLK; // 98

// ---------------- scratch (static device allocations) ----------------
__device__ float g_h[(size_t)NN * 256];   // GEMM output (per layer)
__device__ float g_x[(size_t)NN * 256];   // aggregated + ELU output (next layer input)
__device__ float g_as[NN * 4];            // alpha_src per node per head
__device__ float g_ad[NN * 4];            // alpha_dst per node per head
__device__ float g_inv[NN * 4];           // 1/(denom+eps) per node per head
__device__ float g_att[(size_t)NE * 4];   // exp(e - max) per sorted edge per head
__device__ int   g_cnt[NN];               // in-degree
__device__ int   g_cur[NN];               // scatter cursor
__device__ int   g_row[NN + 1];           // CSR row offsets (by dst)
__device__ int   g_srcs[NE];              // src node id per sorted edge
__device__ int   g_bsum[NB1];             // scan block sums
__device__ float g_wt0[256 * 128];        // W0^T [256][128]
__device__ float g_wt1[256 * 256];        // W1^T [256][256]
__device__ float g_wt2[64 * 256];         // W2^T [64][256]

// ---------------- CSR construction ----------------
__global__ void zero_k() {
    int i = blockIdx.x * blockDim.x + threadIdx.x;
    if (i < NN) { g_cnt[i] = 0; g_cur[i] = 0; }
}

__global__ void deg_k(const int* __restrict__ dst) {
    int e = blockIdx.x * blockDim.x + threadIdx.x;
    if (e < NE) atomicAdd(&g_cnt[dst[e]], 1);
}

__global__ void scan1_k() {
    __shared__ int s[SCAN_BLK];
    int i = blockIdx.x * SCAN_BLK + threadIdx.x;
    int v = (i < NN) ? g_cnt[i] : 0;
    s[threadIdx.x] = v;
    __syncthreads();
    for (int off = 1; off < SCAN_BLK; off <<= 1) {
        int t = (threadIdx.x >= off) ? s[threadIdx.x - off] : 0;
        __syncthreads();
        s[threadIdx.x] += t;
        __syncthreads();
    }
    if (i < NN) g_row[i] = s[threadIdx.x] - v;
    if (threadIdx.x == SCAN_BLK - 1) g_bsum[blockIdx.x] = s[threadIdx.x];
}

__global__ void scan2_k() {
    if (threadIdx.x == 0) {
        int run = 0;
        for (int b = 0; b < NB1; b++) { int t = g_bsum[b]; g_bsum[b] = run; run += t; }
    }
}

__global__ void scan3_k() {
    int i = blockIdx.x * blockDim.x + threadIdx.x;
    if (i < NN) g_row[i] += g_bsum[i / SCAN_BLK];
    if (i == 0) g_row[NN] = NE;
}

__global__ void scatter_k(const int* __restrict__ src, const int* __restrict__ dst) {
    int e = blockIdx.x * blockDim.x + threadIdx.x;
    if (e >= NE) return;
    int d = dst[e];
    int pos = g_row[d] + atomicAdd(&g_cur[d], 1);
    g_srcs[pos] = src[e];
}

// ---------------- weight transpose: W[K,Nc] -> WT[Nc,K] ----------------
template <int WHICH>
__global__ void transpose_k(const float* __restrict__ W, int K, int Nc) {
    float* WT = (WHICH == 0) ? g_wt0 : (WHICH == 1) ? g_wt1 : g_wt2;
    int i = blockIdx.x * blockDim.x + threadIdx.x;
    if (i < K * Nc) {
        int k = i / Nc, n = i - k * Nc;
        WT[(size_t)n * K + k] = W[i];
    }
}

// ---------------- bf16 split-precision tensor-core GEMM ----------------
// C[M,Nc] = A[M,K] @ W[K,Nc], with WT[Nc][K] pre-transposed.
// A,B split into bf16 hi+lo; 3 passes (hh + hl + lh); fp32 accumulate.
__device__ __forceinline__ uint32_t smem_u32(const void* p) {
    uint32_t a;
    asm("{ .reg .u64 t; cvta.to.shared.u64 t, %1; cvt.u32.u64 %0, t; }" : "=r"(a) : "l"(p));
    return a;
}

#define LDMX4(r0, r1, r2, r3, addr) \
    asm volatile("ldmatrix.sync.aligned.m8n8.x4.shared.b16 {%0,%1,%2,%3}, [%4];" \
        : "=r"(r0), "=r"(r1), "=r"(r2), "=r"(r3) : "r"(addr))

#define MMA_BF16(d, a, b) \
    asm volatile("mma.sync.aligned.m16n8k16.row.col.f32.bf16.bf16.f32 " \
        "{%0,%1,%2,%3}, {%4,%5,%6,%7}, {%8,%9}, {%0,%1,%2,%3};" \
        : "+f"((d)[0]), "+f"((d)[1]), "+f"((d)[2]), "+f"((d)[3]) \
        : "r"((a)[0]), "r"((a)[1]), "r"((a)[2]), "r"((a)[3]), "r"((b)[0]), "r"((b)[1]))

template <int BN>
__global__ __launch_bounds__(256) void mma_gemm_k(
    const float* __restrict__ Ain, int use_gx, int K, int which_wt, int Nc) {
    constexpr int WN = BN / 32;          // warps along N
    constexpr int WMW = 8 / WN;          // warps along M
    constexpr int WM = 128 / WMW;        // rows per warp
    constexpr int MT = WM / 16;          // 16-row tiles per warp
    constexpr int PAD = 40;              // bf16 per padded smem row (80B)

    __shared__ __nv_bfloat16 sAh[128][PAD];
    __shared__ __nv_bfloat16 sAl[128][PAD];
    __shared__ __nv_bfloat16 sBh[BN][PAD];
    __shared__ __nv_bfloat16 sBl[BN][PAD];

    const float* A = use_gx ? g_x : Ain;
    const float* WT = (which_wt == 0) ? g_wt0 : (which_wt == 1) ? g_wt1 : g_wt2;

    int tid = threadIdx.x, wid = tid >> 5, lane = tid & 31;
    int warp_m = wid / WN, warp_n = wid % WN;
    int m0 = blockIdx.x * 128, n0 = blockIdx.y * BN;

    uint32_t ah_base = smem_u32(&sAh[0][0]);
    uint32_t al_base = smem_u32(&sAl[0][0]);
    uint32_t bh_base = smem_u32(&sBh[0][0]);
    uint32_t bl_base = smem_u32(&sBl[0][0]);

    float C[MT][4][4];
#pragma unroll
    for (int i = 0; i < MT; i++)
#pragma unroll
        for (int j = 0; j < 4; j++)
#pragma unroll
            for (int c = 0; c < 4; c++) C[i][j][c] = 0.0f;

    // ldmatrix per-thread address components (no .trans: layouts line up for
    // row-major A[m][k] and row-major WT[n][k] with m16n8k16 frag layouts)
    int a_row_off = (lane & 7) + (((lane >> 3) & 1) << 3);
    int a_k_off = (lane >> 4) << 3;
    int b_row_off = (lane & 7) + ((lane >> 4) << 3);  // second pair of 8x8s = next n-tile
    int b_k_off = ((lane >> 3) & 1) << 3;

    for (int k0 = 0; k0 < K; k0 += 32) {
        // ---- load + split A tile (128 x 32 fp32) ----
#pragma unroll
        for (int s = 0; s < 4; s++) {
            int f = tid + s * 256;           // float4 id, 8 per row
            int r = f >> 3, c4 = f & 7;
            float4 v = make_float4(0.f, 0.f, 0.f, 0.f);
            if (m0 + r < NN) v = *(const float4*)(A + (size_t)(m0 + r) * K + k0 + c4 * 4);
            __nv_bfloat16 hx = __float2bfloat16_rn(v.x), hy = __float2bfloat16_rn(v.y);
            __nv_bfloat16 hz = __float2bfloat16_rn(v.z), hw = __float2bfloat16_rn(v.w);
            *(__nv_bfloat162*)&sAh[r][c4 * 4]     = __halves2bfloat162(hx, hy);
            *(__nv_bfloat162*)&sAh[r][c4 * 4 + 2] = __halves2bfloat162(hz, hw);
            __nv_bfloat16 lx = __float2bfloat16_rn(v.x - __bfloat162float(hx));
            __nv_bfloat16 ly = __float2bfloat16_rn(v.y - __bfloat162float(hy));
            __nv_bfloat16 lz = __float2bfloat16_rn(v.z - __bfloat162float(hz));
            __nv_bfloat16 lw = __float2bfloat16_rn(v.w - __bfloat162float(hw));
            *(__nv_bfloat162*)&sAl[r][c4 * 4]     = __halves2bfloat162(lx, ly);
            *(__nv_bfloat162*)&sAl[r][c4 * 4 + 2] = __halves2bfloat162(lz, lw);
        }
        // ---- load + split B tile (BN x 32 fp32 from WT[n][k]) ----
#pragma unroll
        for (int s = 0; s < BN / 32; s++) {
            int f = tid + s * 256;
            int r = f >> 3, c4 = f & 7;
            float4 v = *(const float4*)(WT + (size_t)(n0 + r) * K + k0 + c4 * 4);
            __nv_bfloat16 hx = __float2bfloat16_rn(v.x), hy = __float2bfloat16_rn(v.y);
            __nv_bfloat16 hz = __float2bfloat16_rn(v.z), hw = __float2bfloat16_rn(v.w);
            *(__nv_bfloat162*)&sBh[r][c4 * 4]     = __halves2bfloat162(hx, hy);
            *(__nv_bfloat162*)&sBh[r][c4 * 4 + 2] = __halves2bfloat162(hz, hw);
            __nv_bfloat16 lx = __float2bfloat16_rn(v.x - __bfloat162float(hx));
            __nv_bfloat16 ly = __float2bfloat16_rn(v.y - __bfloat162float(hy));
            __nv_bfloat16 lz = __float2bfloat16_rn(v.z - __bfloat162float(hz));
            __nv_bfloat16 lw = __float2bfloat16_rn(v.w - __bfloat162float(hw));
            *(__nv_bfloat162*)&sBl[r][c4 * 4]     = __halves2bfloat162(lx, ly);
            *(__nv_bfloat162*)&sBl[r][c4 * 4 + 2] = __halves2bfloat162(lz, lw);
        }
        __syncthreads();

#pragma unroll
        for (int kk = 0; kk < 32; kk += 16) {
            uint32_t Ah[MT][4], Al[MT][4];
#pragma unroll
            for (int i = 0; i < MT; i++) {
                uint32_t off = (uint32_t)((warp_m * WM + i * 16 + a_row_off) * PAD + kk + a_k_off) * 2;
                LDMX4(Ah[i][0], Ah[i][1], Ah[i][2], Ah[i][3], ah_base + off);
                LDMX4(Al[i][0], Al[i][1], Al[i][2], Al[i][3], al_base + off);
            }
            uint32_t Bh[4][2], Bl[4][2];
#pragma unroll
            for (int jp = 0; jp < 2; jp++) {   // pairs of n8 tiles
                uint32_t off = (uint32_t)((warp_n * 32 + jp * 16 + b_row_off) * PAD + kk + b_k_off) * 2;
                LDMX4(Bh[jp * 2][0], Bh[jp * 2][1], Bh[jp * 2 + 1][0], Bh[jp * 2 + 1][1], bh_base + off);
                LDMX4(Bl[jp * 2][0], Bl[jp * 2][1], Bl[jp * 2 + 1][0], Bl[jp * 2 + 1][1], bl_base + off);
            }
#pragma unroll
            for (int i = 0; i < MT; i++)
#pragma unroll
                for (int j = 0; j < 4; j++) {
                    MMA_BF16(C[i][j], Ah[i], Bh[j]);
                    MMA_BF16(C[i][j], Ah[i], Bl[j]);
                    MMA_BF16(C[i][j], Al[i], Bh[j]);
                }
        }
        __syncthreads();
    }

    // ---- epilogue: write C to g_h ----
    int gr = m0 + warp_m * WM;
    int gc = n0 + warp_n * 32;
#pragma unroll
    for (int i = 0; i < MT; i++)
#pragma unroll
        for (int j = 0; j < 4; j++) {
            int r0 = gr + i * 16 + (lane >> 2);
            int c = gc + j * 8 + (lane & 3) * 2;
            if (r0 < NN)
                *(float2*)(g_h + (size_t)r0 * Nc + c) = make_float2(C[i][j][0], C[i][j][1]);
            if (r0 + 8 < NN)
                *(float2*)(g_h + (size_t)(r0 + 8) * Nc + c) = make_float2(C[i][j][2], C[i][j][3]);
        }
}

// ---------------- alpha_s / alpha_d per node (warp per node) ----------------
__global__ void alpha_k(const float* __restrict__ avec, int heads, int dim) {
    int warp = (blockIdx.x * blockDim.x + threadIdx.x) >> 5;
    int lane = threadIdx.x & 31;
    if (warp >= NN) return;
    const float* hr = g_h + (size_t)warp * heads * dim;
    for (int hd = 0; hd < heads; hd++) {
        float s = 0.f, dd = 0.f;
        for (int i = lane; i < dim; i += 32) {
            float v = hr[hd * dim + i];
            s  = fmaf(v, avec[hd * 2 * dim + i], s);
            dd = fmaf(v, avec[hd * 2 * dim + dim + i], dd);
        }
#pragma unroll
        for (int off = 16; off; off >>= 1) {
            s  += __shfl_xor_sync(0xffffffffu, s, off);
            dd += __shfl_xor_sync(0xffffffffu, dd, off);
        }
        if (lane == 0) {
            g_as[warp * heads + hd] = s;
            g_ad[warp * heads + hd] = dd;
        }
    }
}

// ---------------- attention softmax (warp per dst node, no atomics) ----------------
template <int H>
__global__ void attn_k() {
    int node = (blockIdx.x * blockDim.x + threadIdx.x) >> 5;
    int lane = threadIdx.x & 31;
    if (node >= NN) return;
    int beg = g_row[node], end = g_row[node + 1];

    float ad[H];
#pragma unroll
    for (int h = 0; h < H; h++) ad[h] = g_ad[node * H + h];

    float m[H];
#pragma unroll
    for (int h = 0; h < H; h++) m[h] = -1e30f;

    for (int i = beg + lane; i < end; i += 32) {
        int sv = g_srcs[i];
#pragma unroll
        for (int h = 0; h < H; h++) {
            float e = g_as[sv * H + h] + ad[h];
            e = (e > 0.f) ? e : 0.2f * e;
            m[h] = fmaxf(m[h], e);
        }
    }
#pragma unroll
    for (int h = 0; h < H; h++)
#pragma unroll
        for (int off = 16; off; off >>= 1)
            m[h] = fmaxf(m[h], __shfl_xor_sync(0xffffffffu, m[h], off));

    float sum[H];
#pragma unroll
    for (int h = 0; h < H; h++) sum[h] = 0.f;

    for (int i = beg + lane; i < end; i += 32) {
        int sv = g_srcs[i];
#pragma unroll
        for (int h = 0; h < H; h++) {
            float e = g_as[sv * H + h] + ad[h];
            e = (e > 0.f) ? e : 0.2f * e;
            float ex = __expf(e - m[h]);
            sum[h] += ex;
            g_att[(size_t)i * H + h] = ex;
        }
    }
#pragma unroll
    for (int h = 0; h < H; h++)
#pragma unroll
        for (int off = 16; off; off >>= 1)
            sum[h] += __shfl_xor_sync(0xffffffffu, sum[h], off);

    if (lane == 0) {
#pragma unroll
        for (int h = 0; h < H; h++)
            g_inv[node * H + h] = 1.0f / (sum[h] + 1e-16f);
    }
}

// ---------------- aggregation, H=4: warp per node, all heads; writes g_x with ELU ----
__global__ void agg4_k() {
    int node = (blockIdx.x * blockDim.x + threadIdx.x) >> 5;
    int lane = threadIdx.x & 31;
    if (node >= NN) return;
    int beg = g_row[node], end = g_row[node + 1];
    int hd = lane >> 3;
    float inv = g_inv[node * 4 + hd];

    float4 acc0 = make_float4(0.f, 0.f, 0.f, 0.f);
    float4 acc1 = make_float4(0.f, 0.f, 0.f, 0.f);

    int sv = (beg < end) ? g_srcs[beg] : 0;
    for (int i = beg; i < end; i++) {
        int svn = (i + 1 < end) ? g_srcs[i + 1] : 0;
        float a = g_att[(size_t)i * 4 + hd] * inv;
        const float* hr = g_h + (size_t)sv * 256 + lane * 8;
        float4 v0 = *(const float4*)(hr);
        float4 v1 = *(const float4*)(hr + 4);
        acc0.x = fmaf(v0.x, a, acc0.x); acc0.y = fmaf(v0.y, a, acc0.y);
        acc0.z = fmaf(v0.z, a, acc0.z); acc0.w = fmaf(v0.w, a, acc0.w);
        acc1.x = fmaf(v1.x, a, acc1.x); acc1.y = fmaf(v1.y, a, acc1.y);
        acc1.z = fmaf(v1.z, a, acc1.z); acc1.w = fmaf(v1.w, a, acc1.w);
        sv = svn;
    }
    acc0.x = (acc0.x > 0.f) ? acc0.x : expm1f(acc0.x);
    acc0.y = (acc0.y > 0.f) ? acc0.y : expm1f(acc0.y);
    acc0.z = (acc0.z > 0.f) ? acc0.z : expm1f(acc0.z);
    acc0.w = (acc0.w > 0.f) ? acc0.w : expm1f(acc0.w);
    acc1.x = (acc1.x > 0.f) ? acc1.x : expm1f(acc1.x);
    acc1.y = (acc1.y > 0.f) ? acc1.y : expm1f(acc1.y);
    acc1.z = (acc1.z > 0.f) ? acc1.z : expm1f(acc1.z);
    acc1.w = (acc1.w > 0.f) ? acc1.w : expm1f(acc1.w);

    float* out = g_x + (size_t)node * 256 + lane * 8;
    *(float4*)(out)     = acc0;
    *(float4*)(out + 4) = acc1;
}

// ---------------- aggregation, H=1 (final layer, writes d_out, no ELU) ----------------
__global__ void agg1_k(float* __restrict__ outp) {
    int node = (blockIdx.x * blockDim.x + threadIdx.x) >> 5;
    int lane = threadIdx.x & 31;
    if (node >= NN) return;
    int beg = g_row[node], end = g_row[node + 1];
    float inv = g_inv[node];

    float ax = 0.f, ay = 0.f;
    int sv = (beg < end) ? g_srcs[beg] : 0;
    for (int i = beg; i < end; i++) {
        int svn = (i + 1 < end) ? g_srcs[i + 1] : 0;
        float a = g_att[i] * inv;
        const float2 hv = *(const float2*)(g_h + (size_t)sv * 64 + lane * 2);
        ax = fmaf(hv.x, a, ax);
        ay = fmaf(hv.y, a, ay);
        sv = svn;
    }
    *(float2*)(outp + (size_t)node * 64 + lane * 2) = make_float2(ax, ay);
}

// ---------------- launch ----------------
extern "C" void kernel_launch(void* const* d_in, const int* in_sizes, int n_in,
                              void* d_out, int out_size) {
    const float* x  = (const float*)d_in[0];
    const int*   ei = (const int*)d_in[1];
    const int*   src = ei;
    const int*   dst = ei + NE;
    const float* W0 = (const float*)d_in[2];
    const float* a0 = (const float*)d_in[3];
    const float* W1 = (const float*)d_in[4];
    const float* a1 = (const float*)d_in[5];
    const float* W2 = (const float*)d_in[6];
    const float* a2 = (const float*)d_in[7];
    float* out = (float*)d_out;

    int node_warp_blocks = (NN + 3) / 4;   // 4 warps / 128-thread block
    int gemm_gx = (NN + 127) / 128;        // 782

    // --- weight transposes (W[K,Nc] -> WT[Nc][K]) ---
    transpose_k<0><<<(128 * 256 + 255) / 256, 256>>>(W0, 128, 256);
    transpose_k<1><<<(256 * 256 + 255) / 256, 256>>>(W1, 256, 256);
    transpose_k<2><<<(256 * 64 + 255) / 256, 256>>>(W2, 256, 64);

    // --- CSR by dst (counting sort) ---
    zero_k<<<(NN + 255) / 256, 256>>>();
    deg_k<<<(NE + 255) / 256, 256>>>(dst);
    scan1_k<<<NB1, SCAN_BLK>>>();
    scan2_k<<<1, 32>>>();
    scan3_k<<<(NN + 255) / 256, 256>>>();
    scatter_k<<<(NE + 255) / 256, 256>>>(src, dst);

    // --- Layer 0: x[N,128] @ W0 -> h[N,256] ---
    mma_gemm_k<128><<<dim3(gemm_gx, 2), 256>>>(x, 0, IN_DIM, 0, 256);
    alpha_k<<<node_warp_blocks, 128>>>(a0, 4, 64);
    attn_k<4><<<node_warp_blocks, 128>>>();
    agg4_k<<<node_warp_blocks, 128>>>();

    // --- Layer 1: g_x[N,256] @ W1 -> h[N,256] ---
    mma_gemm_k<128><<<dim3(gemm_gx, 2), 256>>>(nullptr, 1, 256, 1, 256);
    alpha_k<<<node_warp_blocks, 128>>>(a1, 4, 64);
    attn_k<4><<<node_warp_blocks, 128>>>();
    agg4_k<<<node_warp_blocks, 128>>>();

    // --- Layer 2: g_x[N,256] @ W2 -> h[N,64] ---
    mma_gemm_k<64><<<dim3(gemm_gx, 1), 256>>>(nullptr, 1, 256, 2, 64);
    alpha_k<<<node_warp_blocks, 128>>>(a2, 1, 64);
    attn_k<1><<<node_warp_blocks, 128>>>();
    agg1_k<<<node_warp_blocks, 128>>>(out);
}

// round 15
// speedup vs baseline: 1.4600x; 1.0013x over previous
#include <cuda_runtime.h>
#include <cuda_bf16.h>
#include <math.h>
#include <stdint.h>

// Problem constants
#define NN 100000
#define NE 1600000
#define IN_DIM 128

static constexpr int SCAN_BLK = 1024;
static constexpr int NB1 = (NN + SCAN_BLK - 1) / SCAN_BLK; // 98

// ---------------- scratch (static device allocations) ----------------
__device__ float g_h[(size_t)NN * 256];   // GEMM output (per layer)
__device__ float g_x[(size_t)NN * 256];   // aggregated + ELU output (next layer input)
__device__ float g_as[NN * 4];            // alpha_src per node per head
__device__ float g_ad[NN * 4];            // alpha_dst per node per head
__device__ int   g_cnt[NN];               // in-degree
__device__ int   g_cur[NN];               // scatter cursor
__device__ int   g_row[NN + 1];           // CSR row offsets (by dst)
__device__ int   g_srcs[NE];              // src node id per sorted edge
__device__ int   g_bsum[NB1];             // scan block sums
__device__ float g_wt0[256 * 128];        // W0^T [256][128]
__device__ float g_wt1[256 * 256];        // W1^T [256][256]
__device__ float g_wt2[64 * 256];         // W2^T [64][256]

// ---------------- CSR construction ----------------
__global__ void zero_k() {
    int i = blockIdx.x * blockDim.x + threadIdx.x;
    if (i < NN) { g_cnt[i] = 0; g_cur[i] = 0; }
}

__global__ void deg_k(const int* __restrict__ dst) {
    int e = blockIdx.x * blockDim.x + threadIdx.x;
    if (e < NE) atomicAdd(&g_cnt[dst[e]], 1);
}

__global__ void scan1_k() {
    __shared__ int s[SCAN_BLK];
    int i = blockIdx.x * SCAN_BLK + threadIdx.x;
    int v = (i < NN) ? g_cnt[i] : 0;
    s[threadIdx.x] = v;
    __syncthreads();
    for (int off = 1; off < SCAN_BLK; off <<= 1) {
        int t = (threadIdx.x >= off) ? s[threadIdx.x - off] : 0;
        __syncthreads();
        s[threadIdx.x] += t;
        __syncthreads();
    }
    if (i < NN) g_row[i] = s[threadIdx.x] - v;
    if (threadIdx.x == SCAN_BLK - 1) g_bsum[blockIdx.x] = s[threadIdx.x];
}

__global__ void scan2_k() {
    if (threadIdx.x == 0) {
        int run = 0;
        for (int b = 0; b < NB1; b++) { int t = g_bsum[b]; g_bsum[b] = run; run += t; }
    }
}

__global__ void scan3_k() {
    int i = blockIdx.x * blockDim.x + threadIdx.x;
    if (i < NN) g_row[i] += g_bsum[i / SCAN_BLK];
    if (i == 0) g_row[NN] = NE;
}

__global__ void scatter_k(const int* __restrict__ src, const int* __restrict__ dst) {
    int e = blockIdx.x * blockDim.x + threadIdx.x;
    if (e >= NE) return;
    int d = dst[e];
    int pos = g_row[d] + atomicAdd(&g_cur[d], 1);
    g_srcs[pos] = src[e];
}

// ---------------- weight transpose: W[K,Nc] -> WT[Nc,K] ----------------
template <int WHICH>
__global__ void transpose_k(const float* __restrict__ W, int K, int Nc) {
    float* WT = (WHICH == 0) ? g_wt0 : (WHICH == 1) ? g_wt1 : g_wt2;
    int i = blockIdx.x * blockDim.x + threadIdx.x;
    if (i < K * Nc) {
        int k = i / Nc, n = i - k * Nc;
        WT[(size_t)n * K + k] = W[i];
    }
}

// ---------------- bf16 split-precision tensor-core GEMM ----------------
__device__ __forceinline__ uint32_t smem_u32(const void* p) {
    uint32_t a;
    asm("{ .reg .u64 t; cvta.to.shared.u64 t, %1; cvt.u32.u64 %0, t; }" : "=r"(a) : "l"(p));
    return a;
}

#define LDMX4(r0, r1, r2, r3, addr) \
    asm volatile("ldmatrix.sync.aligned.m8n8.x4.shared.b16 {%0,%1,%2,%3}, [%4];" \
        : "=r"(r0), "=r"(r1), "=r"(r2), "=r"(r3) : "r"(addr))

#define MMA_BF16(d, a, b) \
    asm volatile("mma.sync.aligned.m16n8k16.row.col.f32.bf16.bf16.f32 " \
        "{%0,%1,%2,%3}, {%4,%5,%6,%7}, {%8,%9}, {%0,%1,%2,%3};" \
        : "+f"((d)[0]), "+f"((d)[1]), "+f"((d)[2]), "+f"((d)[3]) \
        : "r"((a)[0]), "r"((a)[1]), "r"((a)[2]), "r"((a)[3]), "r"((b)[0]), "r"((b)[1]))

template <int BN>
__global__ __launch_bounds__(256) void mma_gemm_k(
    const float* __restrict__ Ain, int use_gx, int K, int which_wt, int Nc) {
    constexpr int WN = BN / 32;          // warps along N
    constexpr int WMW = 8 / WN;          // warps along M
    constexpr int WM = 128 / WMW;        // rows per warp
    constexpr int MT = WM / 16;          // 16-row tiles per warp
    constexpr int PAD = 40;              // bf16 per padded smem row (80B)

    __shared__ __nv_bfloat16 sAh[128][PAD];
    __shared__ __nv_bfloat16 sAl[128][PAD];
    __shared__ __nv_bfloat16 sBh[BN][PAD];
    __shared__ __nv_bfloat16 sBl[BN][PAD];

    const float* A = use_gx ? g_x : Ain;
    const float* WT = (which_wt == 0) ? g_wt0 : (which_wt == 1) ? g_wt1 : g_wt2;

    int tid = threadIdx.x, wid = tid >> 5, lane = tid & 31;
    int warp_m = wid / WN, warp_n = wid % WN;
    int m0 = blockIdx.x * 128, n0 = blockIdx.y * BN;

    uint32_t ah_base = smem_u32(&sAh[0][0]);
    uint32_t al_base = smem_u32(&sAl[0][0]);
    uint32_t bh_base = smem_u32(&sBh[0][0]);
    uint32_t bl_base = smem_u32(&sBl[0][0]);

    float C[MT][4][4];
#pragma unroll
    for (int i = 0; i < MT; i++)
#pragma unroll
        for (int j = 0; j < 4; j++)
#pragma unroll
            for (int c = 0; c < 4; c++) C[i][j][c] = 0.0f;

    int a_row_off = (lane & 7) + (((lane >> 3) & 1) << 3);
    int a_k_off = (lane >> 4) << 3;
    int b_row_off = (lane & 7) + ((lane >> 4) << 3);
    int b_k_off = ((lane >> 3) & 1) << 3;

    for (int k0 = 0; k0 < K; k0 += 32) {
        // ---- load + split A tile (128 x 32 fp32) ----
#pragma unroll
        for (int s = 0; s < 4; s++) {
            int f = tid + s * 256;
            int r = f >> 3, c4 = f & 7;
            float4 v = make_float4(0.f, 0.f, 0.f, 0.f);
            if (m0 + r < NN) v = *(const float4*)(A + (size_t)(m0 + r) * K + k0 + c4 * 4);
            __nv_bfloat16 hx = __float2bfloat16_rn(v.x), hy = __float2bfloat16_rn(v.y);
            __nv_bfloat16 hz = __float2bfloat16_rn(v.z), hw = __float2bfloat16_rn(v.w);
            *(__nv_bfloat162*)&sAh[r][c4 * 4]     = __halves2bfloat162(hx, hy);
            *(__nv_bfloat162*)&sAh[r][c4 * 4 + 2] = __halves2bfloat162(hz, hw);
            __nv_bfloat16 lx = __float2bfloat16_rn(v.x - __bfloat162float(hx));
            __nv_bfloat16 ly = __float2bfloat16_rn(v.y - __bfloat162float(hy));
            __nv_bfloat16 lz = __float2bfloat16_rn(v.z - __bfloat162float(hz));
            __nv_bfloat16 lw = __float2bfloat16_rn(v.w - __bfloat162float(hw));
            *(__nv_bfloat162*)&sAl[r][c4 * 4]     = __halves2bfloat162(lx, ly);
            *(__nv_bfloat162*)&sAl[r][c4 * 4 + 2] = __halves2bfloat162(lz, lw);
        }
        // ---- load + split B tile (BN x 32 fp32 from WT[n][k]) ----
#pragma unroll
        for (int s = 0; s < BN / 32; s++) {
            int f = tid + s * 256;
            int r = f >> 3, c4 = f & 7;
            float4 v = *(const float4*)(WT + (size_t)(n0 + r) * K + k0 + c4 * 4);
            __nv_bfloat16 hx = __float2bfloat16_rn(v.x), hy = __float2bfloat16_rn(v.y);
            __nv_bfloat16 hz = __float2bfloat16_rn(v.z), hw = __float2bfloat16_rn(v.w);
            *(__nv_bfloat162*)&sBh[r][c4 * 4]     = __halves2bfloat162(hx, hy);
            *(__nv_bfloat162*)&sBh[r][c4 * 4 + 2] = __halves2bfloat162(hz, hw);
            __nv_bfloat16 lx = __float2bfloat16_rn(v.x - __bfloat162float(hx));
            __nv_bfloat16 ly = __float2bfloat16_rn(v.y - __bfloat162float(hy));
            __nv_bfloat16 lz = __float2bfloat16_rn(v.z - __bfloat162float(hz));
            __nv_bfloat16 lw = __float2bfloat16_rn(v.w - __bfloat162float(hw));
            *(__nv_bfloat162*)&sBl[r][c4 * 4]     = __halves2bfloat162(lx, ly);
            *(__nv_bfloat162*)&sBl[r][c4 * 4 + 2] = __halves2bfloat162(lz, lw);
        }
        __syncthreads();

#pragma unroll
        for (int kk = 0; kk < 32; kk += 16) {
            uint32_t Ah[MT][4], Al[MT][4];
#pragma unroll
            for (int i = 0; i < MT; i++) {
                uint32_t off = (uint32_t)((warp_m * WM + i * 16 + a_row_off) * PAD + kk + a_k_off) * 2;
                LDMX4(Ah[i][0], Ah[i][1], Ah[i][2], Ah[i][3], ah_base + off);
                LDMX4(Al[i][0], Al[i][1], Al[i][2], Al[i][3], al_base + off);
            }
            uint32_t Bh[4][2], Bl[4][2];
#pragma unroll
            for (int jp = 0; jp < 2; jp++) {
                uint32_t off = (uint32_t)((warp_n * 32 + jp * 16 + b_row_off) * PAD + kk + b_k_off) * 2;
                LDMX4(Bh[jp * 2][0], Bh[jp * 2][1], Bh[jp * 2 + 1][0], Bh[jp * 2 + 1][1], bh_base + off);
                LDMX4(Bl[jp * 2][0], Bl[jp * 2][1], Bl[jp * 2 + 1][0], Bl[jp * 2 + 1][1], bl_base + off);
            }
#pragma unroll
            for (int i = 0; i < MT; i++)
#pragma unroll
                for (int j = 0; j < 4; j++) {
                    MMA_BF16(C[i][j], Ah[i], Bh[j]);
                    MMA_BF16(C[i][j], Ah[i], Bl[j]);
                    MMA_BF16(C[i][j], Al[i], Bh[j]);
                }
        }
        __syncthreads();
    }

    int gr = m0 + warp_m * WM;
    int gc = n0 + warp_n * 32;
#pragma unroll
    for (int i = 0; i < MT; i++)
#pragma unroll
        for (int j = 0; j < 4; j++) {
            int r0 = gr + i * 16 + (lane >> 2);
            int c = gc + j * 8 + (lane & 3) * 2;
            if (r0 < NN)
                *(float2*)(g_h + (size_t)r0 * Nc + c) = make_float2(C[i][j][0], C[i][j][1]);
            if (r0 + 8 < NN)
                *(float2*)(g_h + (size_t)(r0 + 8) * Nc + c) = make_float2(C[i][j][2], C[i][j][3]);
        }
}

// ---------------- alpha_s / alpha_d per node (warp per node) ----------------
__global__ void alpha_k(const float* __restrict__ avec, int heads, int dim) {
    int warp = (blockIdx.x * blockDim.x + threadIdx.x) >> 5;
    int lane = threadIdx.x & 31;
    if (warp >= NN) return;
    const float* hr = g_h + (size_t)warp * heads * dim;
    for (int hd = 0; hd < heads; hd++) {
        float s = 0.f, dd = 0.f;
        for (int i = lane; i < dim; i += 32) {
            float v = hr[hd * dim + i];
            s  = fmaf(v, avec[hd * 2 * dim + i], s);
            dd = fmaf(v, avec[hd * 2 * dim + dim + i], dd);
        }
#pragma unroll
        for (int off = 16; off; off >>= 1) {
            s  += __shfl_xor_sync(0xffffffffu, s, off);
            dd += __shfl_xor_sync(0xffffffffu, dd, off);
        }
        if (lane == 0) {
            g_as[warp * heads + hd] = s;
            g_ad[warp * heads + hd] = dd;
        }
    }
}

// ---------------- fused softmax + aggregation (warp per node) ----------------
// Pass1: gather e, cache in regs (CAP slots/lane), warp-max.
// Pass2: exp from cache, warp-sum -> inv.
// Pass3: aggregate h[src] * exp (shfl-broadcast from owner lane), scale by inv.
template <int H, bool LAST>
__global__ __launch_bounds__(128) void attn_agg_k(float* __restrict__ outp) {
    constexpr int CAP = 4;                 // cached edge slots per lane (deg <= 128 fast path)
    const unsigned FULL = 0xffffffffu;
    int node = (blockIdx.x * blockDim.x + threadIdx.x) >> 5;
    int lane = threadIdx.x & 31;
    if (node >= NN) return;
    int beg = g_row[node], end = g_row[node + 1];

    float ad[H];
#pragma unroll
    for (int h = 0; h < H; h++) ad[h] = g_ad[node * H + h];

    float ec[CAP][H];
    float mx[H];
#pragma unroll
    for (int h = 0; h < H; h++) mx[h] = -1e30f;

    // ---- pass 1: gather + leaky, cache, max ----
#pragma unroll
    for (int slot = 0; slot < CAP; slot++) {
        int i = beg + slot * 32 + lane;
        if (i < end) {
            int sv = g_srcs[i];
#pragma unroll
            for (int h = 0; h < H; h++) {
                float e = g_as[sv * H + h] + ad[h];
                e = (e > 0.f) ? e : 0.2f * e;
                ec[slot][h] = e;
                mx[h] = fmaxf(mx[h], e);
            }
        }
    }
    for (int i = beg + CAP * 32 + lane; i < end; i += 32) {
        int sv = g_srcs[i];
#pragma unroll
        for (int h = 0; h < H; h++) {
            float e = g_as[sv * H + h] + ad[h];
            e = (e > 0.f) ? e : 0.2f * e;
            mx[h] = fmaxf(mx[h], e);
        }
    }
#pragma unroll
    for (int h = 0; h < H; h++)
#pragma unroll
        for (int off = 16; off; off >>= 1)
            mx[h] = fmaxf(mx[h], __shfl_xor_sync(FULL, mx[h], off));

    // ---- pass 2: exp + sum (cache becomes exp values) ----
    float sum[H];
#pragma unroll
    for (int h = 0; h < H; h++) sum[h] = 0.f;
#pragma unroll
    for (int slot = 0; slot < CAP; slot++) {
        int i = beg + slot * 32 + lane;
        if (i < end) {
#pragma unroll
            for (int h = 0; h < H; h++) {
                float ex = __expf(ec[slot][h] - mx[h]);
                ec[slot][h] = ex;
                sum[h] += ex;
            }
        }
    }
    for (int i = beg + CAP * 32 + lane; i < end; i += 32) {
        int sv = g_srcs[i];
#pragma unroll
        for (int h = 0; h < H; h++) {
            float e = g_as[sv * H + h] + ad[h];
            e = (e > 0.f) ? e : 0.2f * e;
            sum[h] += __expf(e - mx[h]);
        }
    }
#pragma unroll
    for (int h = 0; h < H; h++)
#pragma unroll
        for (int off = 16; off; off >>= 1)
            sum[h] += __shfl_xor_sync(FULL, sum[h], off);

    // ---- pass 3: aggregate ----
    if (LAST) {
        float inv = 1.0f / (sum[0] + 1e-16f);
        float ax = 0.f, ay = 0.f;
        int i = beg;
#pragma unroll
        for (int slot = 0; slot < CAP; slot++) {
            int ce = min(end, beg + (slot + 1) * 32);
            for (int owner = 0; i < ce; i++, owner++) {
                float att = __shfl_sync(FULL, ec[slot][0], owner);
                int sv = g_srcs[i];
                const float2 hv = *(const float2*)(g_h + (size_t)sv * 64 + lane * 2);
                ax = fmaf(hv.x, att, ax);
                ay = fmaf(hv.y, att, ay);
            }
        }
        for (; i < end; i++) {
            int sv = g_srcs[i];
            float e = g_as[sv] + ad[0];
            e = (e > 0.f) ? e : 0.2f * e;
            float att = __expf(e - mx[0]);
            const float2 hv = *(const float2*)(g_h + (size_t)sv * 64 + lane * 2);
            ax = fmaf(hv.x, att, ax);
            ay = fmaf(hv.y, att, ay);
        }
        *(float2*)(outp + (size_t)node * 64 + lane * 2) = make_float2(ax * inv, ay * inv);
    } else {
        int hd = lane >> 3;  // head of this lane's 8-float slice
        float ad_m = (hd < 2) ? ((hd == 0) ? ad[0] : ad[1]) : ((hd == 2) ? ad[2] : ad[3]);
        float mx_m = (hd < 2) ? ((hd == 0) ? mx[0] : mx[1]) : ((hd == 2) ? mx[2] : mx[3]);
        float sum_m = (hd < 2) ? ((hd == 0) ? sum[0] : sum[1]) : ((hd == 2) ? sum[2] : sum[3]);
        float inv = 1.0f / (sum_m + 1e-16f);

        float4 acc0 = make_float4(0.f, 0.f, 0.f, 0.f);
        float4 acc1 = make_float4(0.f, 0.f, 0.f, 0.f);
        int i = beg;
#pragma unroll
        for (int slot = 0; slot < CAP; slot++) {
            int ce = min(end, beg + (slot + 1) * 32);
            for (int owner = 0; i < ce; i++, owner++) {
                float e0 = __shfl_sync(FULL, ec[slot][0], owner);
                float e1 = __shfl_sync(FULL, ec[slot][1], owner);
                float e2 = __shfl_sync(FULL, ec[slot][2], owner);
                float e3 = __shfl_sync(FULL, ec[slot][3], owner);
                float att = (hd < 2) ? ((hd == 0) ? e0 : e1) : ((hd == 2) ? e2 : e3);
                int sv = g_srcs[i];
                const float* hr = g_h + (size_t)sv * 256 + lane * 8;
                float4 v0 = *(const float4*)(hr);
                float4 v1 = *(const float4*)(hr + 4);
                acc0.x = fmaf(v0.x, att, acc0.x); acc0.y = fmaf(v0.y, att, acc0.y);
                acc0.z = fmaf(v0.z, att, acc0.z); acc0.w = fmaf(v0.w, att, acc0.w);
                acc1.x = fmaf(v1.x, att, acc1.x); acc1.y = fmaf(v1.y, att, acc1.y);
                acc1.z = fmaf(v1.z, att, acc1.z); acc1.w = fmaf(v1.w, att, acc1.w);
            }
        }
        for (; i < end; i++) {
            int sv = g_srcs[i];
            float e = g_as[sv * 4 + hd] + ad_m;
            e = (e > 0.f) ? e : 0.2f * e;
            float att = __expf(e - mx_m);
            const float* hr = g_h + (size_t)sv * 256 + lane * 8;
            float4 v0 = *(const float4*)(hr);
            float4 v1 = *(const float4*)(hr + 4);
            acc0.x = fmaf(v0.x, att, acc0.x); acc0.y = fmaf(v0.y, att, acc0.y);
            acc0.z = fmaf(v0.z, att, acc0.z); acc0.w = fmaf(v0.w, att, acc0.w);
            acc1.x = fmaf(v1.x, att, acc1.x); acc1.y = fmaf(v1.y, att, acc1.y);
            acc1.z = fmaf(v1.z, att, acc1.z); acc1.w = fmaf(v1.w, att, acc1.w);
        }
        // normalize + ELU
        acc0.x *= inv; acc0.y *= inv; acc0.z *= inv; acc0.w *= inv;
        acc1.x *= inv; acc1.y *= inv; acc1.z *= inv; acc1.w *= inv;
        acc0.x = (acc0.x > 0.f) ? acc0.x : expm1f(acc0.x);
        acc0.y = (acc0.y > 0.f) ? acc0.y : expm1f(acc0.y);
        acc0.z = (acc0.z > 0.f) ? acc0.z : expm1f(acc0.z);
        acc0.w = (acc0.w > 0.f) ? acc0.w : expm1f(acc0.w);
        acc1.x = (acc1.x > 0.f) ? acc1.x : expm1f(acc1.x);
        acc1.y = (acc1.y > 0.f) ? acc1.y : expm1f(acc1.y);
        acc1.z = (acc1.z > 0.f) ? acc1.z : expm1f(acc1.z);
        acc1.w = (acc1.w > 0.f) ? acc1.w : expm1f(acc1.w);

        float* out = g_x + (size_t)node * 256 + lane * 8;
        *(float4*)(out)     = acc0;
        *(float4*)(out + 4) = acc1;
    }
}

// ---------------- launch ----------------
extern "C" void kernel_launch(void* const* d_in, const int* in_sizes, int n_in,
                              void* d_out, int out_size) {
    const float* x  = (const float*)d_in[0];
    const int*   ei = (const int*)d_in[1];
    const int*   src = ei;
    const int*   dst = ei + NE;
    const float* W0 = (const float*)d_in[2];
    const float* a0 = (const float*)d_in[3];
    const float* W1 = (const float*)d_in[4];
    const float* a1 = (const float*)d_in[5];
    const float* W2 = (const float*)d_in[6];
    const float* a2 = (const float*)d_in[7];
    float* out = (float*)d_out;

    int node_warp_blocks = (NN + 3) / 4;   // 4 warps / 128-thread block
    int gemm_gx = (NN + 127) / 128;        // 782

    // --- weight transposes (launches 0-2) ---
    transpose_k<0><<<(128 * 256 + 255) / 256, 256>>>(W0, 128, 256);
    transpose_k<1><<<(256 * 256 + 255) / 256, 256>>>(W1, 256, 256);
    transpose_k<2><<<(256 * 64 + 255) / 256, 256>>>(W2, 256, 64);

    // --- Layer 0 GEMM at launch index 3 (gets profiled by ncu) ---
    mma_gemm_k<128><<<dim3(gemm_gx, 2), 256>>>(x, 0, IN_DIM, 0, 256);

    // --- CSR by dst (counting sort) ---
    zero_k<<<(NN + 255) / 256, 256>>>();
    deg_k<<<(NE + 255) / 256, 256>>>(dst);
    scan1_k<<<NB1, SCAN_BLK>>>();
    scan2_k<<<1, 32>>>();
    scan3_k<<<(NN + 255) / 256, 256>>>();
    scatter_k<<<(NE + 255) / 256, 256>>>(src, dst);

    // --- Layer 0 edge phase ---
    alpha_k<<<node_warp_blocks, 128>>>(a0, 4, 64);
    attn_agg_k<4, false><<<node_warp_blocks, 128>>>(nullptr);

    // --- Layer 1 ---
    mma_gemm_k<128><<<dim3(gemm_gx, 2), 256>>>(nullptr, 1, 256, 1, 256);
    alpha_k<<<node_warp_blocks, 128>>>(a1, 4, 64);
    attn_agg_k<4, false><<<node_warp_blocks, 128>>>(nullptr);

    // --- Layer 2 ---
    mma_gemm_k<64><<<dim3(gemm_gx, 1), 256>>>(nullptr, 1, 256, 2, 64);
    alpha_k<<<node_warp_blocks, 128>>>(a2, 1, 64);
    attn_agg_k<1, true><<<node_warp_blocks, 128>>>(out);
}

// round 16
// speedup vs baseline: 1.6650x; 1.1404x over previous
#include <cuda_runtime.h>
#include <cuda_bf16.h>
#include <math.h>
#include <stdint.h>

// Problem constants
#define NN 100000
#define NE 1600000
#define IN_DIM 128

static constexpr int SCAN_BLK = 1024;
static constexpr int NB1 = (NN + SCAN_BLK - 1) / SCAN_BLK; // 98

// ---------------- scratch (static device allocations) ----------------
__device__ float g_h[(size_t)NN * 256];   // GEMM output (per layer)
__device__ float g_x[(size_t)NN * 256];   // aggregated + ELU output (next layer input)
__device__ float g_as[NN * 4];            // alpha_src per node per head
__device__ float g_ad[NN * 4];            // alpha_dst per node per head
__device__ int   g_cnt[NN];               // in-degree
__device__ int   g_cur[NN];               // scatter cursor
__device__ int   g_row[NN + 1];           // CSR row offsets (by dst)
__device__ int   g_srcs[NE];              // src node id per sorted edge
__device__ int   g_bsum[NB1];             // scan block sums
// pre-split transposed weights, bf16 hi/lo: [Nc][K]
__device__ __nv_bfloat16 g_wbh0[256 * 128], g_wbl0[256 * 128];
__device__ __nv_bfloat16 g_wbh1[256 * 256], g_wbl1[256 * 256];
__device__ __nv_bfloat16 g_wbh2[64 * 256],  g_wbl2[64 * 256];

// ---------------- CSR construction ----------------
__global__ void zero_k() {
    int i = blockIdx.x * blockDim.x + threadIdx.x;
    if (i < NN) { g_cnt[i] = 0; g_cur[i] = 0; }
}

__global__ void zero_asad_k() {
    int i = blockIdx.x * blockDim.x + threadIdx.x;
    if (i < NN * 4) { g_as[i] = 0.f; g_ad[i] = 0.f; }
}

__global__ void deg_k(const int* __restrict__ dst) {
    int e = blockIdx.x * blockDim.x + threadIdx.x;
    if (e < NE) atomicAdd(&g_cnt[dst[e]], 1);
}

__global__ void scan1_k() {
    __shared__ int s[SCAN_BLK];
    int i = blockIdx.x * SCAN_BLK + threadIdx.x;
    int v = (i < NN) ? g_cnt[i] : 0;
    s[threadIdx.x] = v;
    __syncthreads();
    for (int off = 1; off < SCAN_BLK; off <<= 1) {
        int t = (threadIdx.x >= off) ? s[threadIdx.x - off] : 0;
        __syncthreads();
        s[threadIdx.x] += t;
        __syncthreads();
    }
    if (i < NN) g_row[i] = s[threadIdx.x] - v;
    if (threadIdx.x == SCAN_BLK - 1) g_bsum[blockIdx.x] = s[threadIdx.x];
}

__global__ void scan2_k() {
    if (threadIdx.x == 0) {
        int run = 0;
        for (int b = 0; b < NB1; b++) { int t = g_bsum[b]; g_bsum[b] = run; run += t; }
    }
}

__global__ void scan3_k() {
    int i = blockIdx.x * blockDim.x + threadIdx.x;
    if (i < NN) g_row[i] += g_bsum[i / SCAN_BLK];
    if (i == 0) g_row[NN] = NE;
}

__global__ void scatter_k(const int* __restrict__ src, const int* __restrict__ dst) {
    int e = blockIdx.x * blockDim.x + threadIdx.x;
    if (e >= NE) return;
    int d = dst[e];
    int pos = g_row[d] + atomicAdd(&g_cur[d], 1);
    g_srcs[pos] = src[e];
}

// ---------------- weight transpose + bf16 hi/lo split ----------------
template <int WHICH>
__global__ void wsplit_k(const float* __restrict__ W) {
    constexpr int K  = (WHICH == 0) ? 128 : 256;
    constexpr int Nc = (WHICH == 2) ? 64 : 256;
    __nv_bfloat16* Bh = (WHICH == 0) ? g_wbh0 : (WHICH == 1) ? g_wbh1 : g_wbh2;
    __nv_bfloat16* Bl = (WHICH == 0) ? g_wbl0 : (WHICH == 1) ? g_wbl1 : g_wbl2;
    int i = blockIdx.x * blockDim.x + threadIdx.x;
    if (i < K * Nc) {
        int k = i / Nc, n = i - k * Nc;
        float v = W[i];
        __nv_bfloat16 h = __float2bfloat16_rn(v);
        __nv_bfloat16 l = __float2bfloat16_rn(v - __bfloat162float(h));
        Bh[(size_t)n * K + k] = h;
        Bl[(size_t)n * K + k] = l;
    }
}

// ---------------- bf16 split-precision tensor-core GEMM + fused alpha ----------------
__device__ __forceinline__ uint32_t smem_u32(const void* p) {
    uint32_t a;
    asm("{ .reg .u64 t; cvta.to.shared.u64 t, %1; cvt.u32.u64 %0, t; }" : "=r"(a) : "l"(p));
    return a;
}

#define LDMX4(r0, r1, r2, r3, addr) \
    asm volatile("ldmatrix.sync.aligned.m8n8.x4.shared.b16 {%0,%1,%2,%3}, [%4];" \
        : "=r"(r0), "=r"(r1), "=r"(r2), "=r"(r3) : "r"(addr))

#define MMA_BF16(d, a, b) \
    asm volatile("mma.sync.aligned.m16n8k16.row.col.f32.bf16.bf16.f32 " \
        "{%0,%1,%2,%3}, {%4,%5,%6,%7}, {%8,%9}, {%0,%1,%2,%3};" \
        : "+f"((d)[0]), "+f"((d)[1]), "+f"((d)[2]), "+f"((d)[3]) \
        : "r"((a)[0]), "r"((a)[1]), "r"((a)[2]), "r"((a)[3]), "r"((b)[0]), "r"((b)[1]))

template <int BN>
__global__ __launch_bounds__(256, 2) void mma_gemm_k(
    const float* __restrict__ Ain, int use_gx, int K, int which, int Nc,
    const float* __restrict__ avec, int H) {
    constexpr int WN = BN / 32;          // warps along N
    constexpr int WMW = 8 / WN;          // warps along M
    constexpr int WM = 128 / WMW;        // rows per warp
    constexpr int MT = WM / 16;          // 16-row tiles per warp
    constexpr int PAD = 40;              // bf16 per padded smem row (80B)

    __shared__ __nv_bfloat16 sAh[128][PAD];
    __shared__ __nv_bfloat16 sAl[128][PAD];
    __shared__ __nv_bfloat16 sBh[BN][PAD];
    __shared__ __nv_bfloat16 sBl[BN][PAD];
    __shared__ float s_avec[512];

    const float* A = use_gx ? g_x : Ain;
    const __nv_bfloat16* WBh = (which == 0) ? g_wbh0 : (which == 1) ? g_wbh1 : g_wbh2;
    const __nv_bfloat16* WBl = (which == 0) ? g_wbl0 : (which == 1) ? g_wbl1 : g_wbl2;

    int tid = threadIdx.x, wid = tid >> 5, lane = tid & 31;
    int warp_m = wid / WN, warp_n = wid % WN;
    int m0 = blockIdx.x * 128, n0 = blockIdx.y * BN;

    for (int i = tid; i < H * 128; i += 256) s_avec[i] = avec[i];

    uint32_t ah_base = smem_u32(&sAh[0][0]);
    uint32_t al_base = smem_u32(&sAl[0][0]);
    uint32_t bh_base = smem_u32(&sBh[0][0]);
    uint32_t bl_base = smem_u32(&sBl[0][0]);

    float C[MT][4][4];
#pragma unroll
    for (int i = 0; i < MT; i++)
#pragma unroll
        for (int j = 0; j < 4; j++)
#pragma unroll
            for (int c = 0; c < 4; c++) C[i][j][c] = 0.0f;

    int a_row_off = (lane & 7) + (((lane >> 3) & 1) << 3);
    int a_k_off = (lane >> 4) << 3;
    int b_row_off = (lane & 7) + ((lane >> 4) << 3);
    int b_k_off = ((lane >> 3) & 1) << 3;

    // ---- prefetch A tile 0 into regs ----
    float4 av[4];
#pragma unroll
    for (int s = 0; s < 4; s++) {
        int f = tid + s * 256;
        int r = f >> 3, c4 = f & 7;
        av[s] = (m0 + r < NN) ? *(const float4*)(A + (size_t)(m0 + r) * K + c4 * 4)
                              : make_float4(0.f, 0.f, 0.f, 0.f);
    }

    for (int k0 = 0; k0 < K; k0 += 32) {
        // ---- B tile regs (bf16, pre-split, L2-hot) ----
        uint4 bh0, bh1, bl0, bl1;
        int br, bk;
        if (BN == 128) {
            br = tid >> 1; bk = (tid & 1) * 16;
            const __nv_bfloat16* ph = WBh + (size_t)(n0 + br) * K + k0 + bk;
            const __nv_bfloat16* pl = WBl + (size_t)(n0 + br) * K + k0 + bk;
            bh0 = *(const uint4*)(ph); bh1 = *(const uint4*)(ph + 8);
            bl0 = *(const uint4*)(pl); bl1 = *(const uint4*)(pl + 8);
        } else {
            br = tid >> 2; bk = (tid & 3) * 8;
            bh0 = *(const uint4*)(WBh + (size_t)(n0 + br) * K + k0 + bk);
            bl0 = *(const uint4*)(WBl + (size_t)(n0 + br) * K + k0 + bk);
        }

        __syncthreads();  // previous compute done (smem free)

        // ---- store A (convert to hi/lo) + B tiles ----
#pragma unroll
        for (int s = 0; s < 4; s++) {
            int f = tid + s * 256;
            int r = f >> 3, c4 = f & 7;
            float4 v = av[s];
            __nv_bfloat16 hx = __float2bfloat16_rn(v.x), hy = __float2bfloat16_rn(v.y);
            __nv_bfloat16 hz = __float2bfloat16_rn(v.z), hw = __float2bfloat16_rn(v.w);
            *(__nv_bfloat162*)&sAh[r][c4 * 4]     = __halves2bfloat162(hx, hy);
            *(__nv_bfloat162*)&sAh[r][c4 * 4 + 2] = __halves2bfloat162(hz, hw);
            __nv_bfloat16 lx = __float2bfloat16_rn(v.x - __bfloat162float(hx));
            __nv_bfloat16 ly = __float2bfloat16_rn(v.y - __bfloat162float(hy));
            __nv_bfloat16 lz = __float2bfloat16_rn(v.z - __bfloat162float(hz));
            __nv_bfloat16 lw = __float2bfloat16_rn(v.w - __bfloat162float(hw));
            *(__nv_bfloat162*)&sAl[r][c4 * 4]     = __halves2bfloat162(lx, ly);
            *(__nv_bfloat162*)&sAl[r][c4 * 4 + 2] = __halves2bfloat162(lz, lw);
        }
        *(uint4*)&sBh[br][bk] = bh0;
        *(uint4*)&sBl[br][bk] = bl0;
        if (BN == 128) {
            *(uint4*)&sBh[br][bk + 8] = bh1;
            *(uint4*)&sBl[br][bk + 8] = bl1;
        }
        __syncthreads();

        // ---- prefetch next A tile (overlaps with MMA below) ----
        if (k0 + 32 < K) {
#pragma unroll
            for (int s = 0; s < 4; s++) {
                int f = tid + s * 256;
                int r = f >> 3, c4 = f & 7;
                av[s] = (m0 + r < NN)
                    ? *(const float4*)(A + (size_t)(m0 + r) * K + (k0 + 32) + c4 * 4)
                    : make_float4(0.f, 0.f, 0.f, 0.f);
            }
        }

        // ---- compute ----
#pragma unroll
        for (int kk = 0; kk < 32; kk += 16) {
            uint32_t Ah[MT][4], Al[MT][4];
#pragma unroll
            for (int i = 0; i < MT; i++) {
                uint32_t off = (uint32_t)((warp_m * WM + i * 16 + a_row_off) * PAD + kk + a_k_off) * 2;
                LDMX4(Ah[i][0], Ah[i][1], Ah[i][2], Ah[i][3], ah_base + off);
                LDMX4(Al[i][0], Al[i][1], Al[i][2], Al[i][3], al_base + off);
            }
            uint32_t Bh[4][2], Bl[4][2];
#pragma unroll
            for (int jp = 0; jp < 2; jp++) {
                uint32_t off = (uint32_t)((warp_n * 32 + jp * 16 + b_row_off) * PAD + kk + b_k_off) * 2;
                LDMX4(Bh[jp * 2][0], Bh[jp * 2][1], Bh[jp * 2 + 1][0], Bh[jp * 2 + 1][1], bh_base + off);
                LDMX4(Bl[jp * 2][0], Bl[jp * 2][1], Bl[jp * 2 + 1][0], Bl[jp * 2 + 1][1], bl_base + off);
            }
#pragma unroll
            for (int i = 0; i < MT; i++)
#pragma unroll
                for (int j = 0; j < 4; j++) {
                    MMA_BF16(C[i][j], Ah[i], Bh[j]);
                    MMA_BF16(C[i][j], Ah[i], Bl[j]);
                    MMA_BF16(C[i][j], Al[i], Bh[j]);
                }
        }
    }

    // ---- epilogue: write C + fused alpha partial dots ----
    int gr = m0 + warp_m * WM;
    int gc = n0 + warp_n * 32;
    int head = gc >> 6;          // each warp tile lies within one 64-col head
    int wbase = gc & 63;
#pragma unroll
    for (int i = 0; i < MT; i++) {
        int r0 = gr + i * 16 + (lane >> 2);
        float aS0 = 0.f, aD0 = 0.f, aS1 = 0.f, aD1 = 0.f;
#pragma unroll
        for (int j = 0; j < 4; j++) {
            int wc = wbase + j * 8 + (lane & 3) * 2;
            float s0 = s_avec[head * 128 + wc],      s1 = s_avec[head * 128 + wc + 1];
            float d0 = s_avec[head * 128 + 64 + wc], d1 = s_avec[head * 128 + 64 + wc + 1];
            aS0 = fmaf(C[i][j][0], s0, fmaf(C[i][j][1], s1, aS0));
            aD0 = fmaf(C[i][j][0], d0, fmaf(C[i][j][1], d1, aD0));
            aS1 = fmaf(C[i][j][2], s0, fmaf(C[i][j][3], s1, aS1));
            aD1 = fmaf(C[i][j][2], d0, fmaf(C[i][j][3], d1, aD1));
            int c = gc + j * 8 + (lane & 3) * 2;
            if (r0 < NN)
                *(float2*)(g_h + (size_t)r0 * Nc + c) = make_float2(C[i][j][0], C[i][j][1]);
            if (r0 + 8 < NN)
                *(float2*)(g_h + (size_t)(r0 + 8) * Nc + c) = make_float2(C[i][j][2], C[i][j][3]);
        }
        // reduce over the 4 lanes of the quad (cols)
        const unsigned FULL = 0xffffffffu;
        aS0 += __shfl_xor_sync(FULL, aS0, 1); aS0 += __shfl_xor_sync(FULL, aS0, 2);
        aD0 += __shfl_xor_sync(FULL, aD0, 1); aD0 += __shfl_xor_sync(FULL, aD0, 2);
        aS1 += __shfl_xor_sync(FULL, aS1, 1); aS1 += __shfl_xor_sync(FULL, aS1, 2);
        aD1 += __shfl_xor_sync(FULL, aD1, 1); aD1 += __shfl_xor_sync(FULL, aD1, 2);
        if ((lane & 3) == 0) {
            if (r0 < NN) {
                atomicAdd(&g_as[r0 * H + head], aS0);
                atomicAdd(&g_ad[r0 * H + head], aD0);
            }
            if (r0 + 8 < NN) {
                atomicAdd(&g_as[(r0 + 8) * H + head], aS1);
                atomicAdd(&g_ad[(r0 + 8) * H + head], aD1);
            }
        }
    }
}

// ---------------- fused softmax + aggregation (warp per node) ----------------
template <int H, bool LAST>
__global__ __launch_bounds__(128) void attn_agg_k(float* __restrict__ outp) {
    constexpr int CAP = 4;                 // cached edge slots per lane (deg <= 128 fast path)
    const unsigned FULL = 0xffffffffu;
    int node = (blockIdx.x * blockDim.x + threadIdx.x) >> 5;
    int lane = threadIdx.x & 31;
    if (node >= NN) return;
    int beg = g_row[node], end = g_row[node + 1];

    float ad[H];
#pragma unroll
    for (int h = 0; h < H; h++) ad[h] = g_ad[node * H + h];

    float ec[CAP][H];
    float mx[H];
#pragma unroll
    for (int h = 0; h < H; h++) mx[h] = -1e30f;

    // ---- pass 1: gather + leaky, cache, max ----
#pragma unroll
    for (int slot = 0; slot < CAP; slot++) {
        int i = beg + slot * 32 + lane;
        if (i < end) {
            int sv = g_srcs[i];
#pragma unroll
            for (int h = 0; h < H; h++) {
                float e = g_as[sv * H + h] + ad[h];
                e = (e > 0.f) ? e : 0.2f * e;
                ec[slot][h] = e;
                mx[h] = fmaxf(mx[h], e);
            }
        }
    }
    for (int i = beg + CAP * 32 + lane; i < end; i += 32) {
        int sv = g_srcs[i];
#pragma unroll
        for (int h = 0; h < H; h++) {
            float e = g_as[sv * H + h] + ad[h];
            e = (e > 0.f) ? e : 0.2f * e;
            mx[h] = fmaxf(mx[h], e);
        }
    }
#pragma unroll
    for (int h = 0; h < H; h++)
#pragma unroll
        for (int off = 16; off; off >>= 1)
            mx[h] = fmaxf(mx[h], __shfl_xor_sync(FULL, mx[h], off));

    // ---- pass 2: exp + sum ----
    float sum[H];
#pragma unroll
    for (int h = 0; h < H; h++) sum[h] = 0.f;
#pragma unroll
    for (int slot = 0; slot < CAP; slot++) {
        int i = beg + slot * 32 + lane;
        if (i < end) {
#pragma unroll
            for (int h = 0; h < H; h++) {
                float ex = __expf(ec[slot][h] - mx[h]);
                ec[slot][h] = ex;
                sum[h] += ex;
            }
        }
    }
    for (int i = beg + CAP * 32 + lane; i < end; i += 32) {
        int sv = g_srcs[i];
#pragma unroll
        for (int h = 0; h < H; h++) {
            float e = g_as[sv * H + h] + ad[h];
            e = (e > 0.f) ? e : 0.2f * e;
            sum[h] += __expf(e - mx[h]);
        }
    }
#pragma unroll
    for (int h = 0; h < H; h++)
#pragma unroll
        for (int off = 16; off; off >>= 1)
            sum[h] += __shfl_xor_sync(FULL, sum[h], off);

    // ---- pass 3: aggregate ----
    if (LAST) {
        float inv = 1.0f / (sum[0] + 1e-16f);
        float ax = 0.f, ay = 0.f;
        int i = beg;
#pragma unroll
        for (int slot = 0; slot < CAP; slot++) {
            int ce = min(end, beg + (slot + 1) * 32);
            for (int owner = 0; i < ce; i++, owner++) {
                float att = __shfl_sync(FULL, ec[slot][0], owner);
                int sv = g_srcs[i];
                const float2 hv = *(const float2*)(g_h + (size_t)sv * 64 + lane * 2);
                ax = fmaf(hv.x, att, ax);
                ay = fmaf(hv.y, att, ay);
            }
        }
        for (; i < end; i++) {
            int sv = g_srcs[i];
            float e = g_as[sv] + ad[0];
            e = (e > 0.f) ? e : 0.2f * e;
            float att = __expf(e - mx[0]);
            const float2 hv = *(const float2*)(g_h + (size_t)sv * 64 + lane * 2);
            ax = fmaf(hv.x, att, ax);
            ay = fmaf(hv.y, att, ay);
        }
        *(float2*)(outp + (size_t)node * 64 + lane * 2) = make_float2(ax * inv, ay * inv);
    } else {
        int hd = lane >> 3;  // head of this lane's 8-float slice
        float ad_m = (hd < 2) ? ((hd == 0) ? ad[0] : ad[1]) : ((hd == 2) ? ad[2] : ad[3]);
        float mx_m = (hd < 2) ? ((hd == 0) ? mx[0] : mx[1]) : ((hd == 2) ? mx[2] : mx[3]);
        float sum_m = (hd < 2) ? ((hd == 0) ? sum[0] : sum[1]) : ((hd == 2) ? sum[2] : sum[3]);
        float inv = 1.0f / (sum_m + 1e-16f);

        float4 acc0 = make_float4(0.f, 0.f, 0.f, 0.f);
        float4 acc1 = make_float4(0.f, 0.f, 0.f, 0.f);
        int i = beg;
#pragma unroll
        for (int slot = 0; slot < CAP; slot++) {
            int ce = min(end, beg + (slot + 1) * 32);
            for (int owner = 0; i < ce; i++, owner++) {
                float e0 = __shfl_sync(FULL, ec[slot][0], owner);
                float e1 = __shfl_sync(FULL, ec[slot][1], owner);
                float e2 = __shfl_sync(FULL, ec[slot][2], owner);
                float e3 = __shfl_sync(FULL, ec[slot][3], owner);
                float att = (hd < 2) ? ((hd == 0) ? e0 : e1) : ((hd == 2) ? e2 : e3);
                int sv = g_srcs[i];
                const float* hr = g_h + (size_t)sv * 256 + lane * 8;
                float4 v0 = *(const float4*)(hr);
                float4 v1 = *(const float4*)(hr + 4);
                acc0.x = fmaf(v0.x, att, acc0.x); acc0.y = fmaf(v0.y, att, acc0.y);
                acc0.z = fmaf(v0.z, att, acc0.z); acc0.w = fmaf(v0.w, att, acc0.w);
                acc1.x = fmaf(v1.x, att, acc1.x); acc1.y = fmaf(v1.y, att, acc1.y);
                acc1.z = fmaf(v1.z, att, acc1.z); acc1.w = fmaf(v1.w, att, acc1.w);
            }
        }
        for (; i < end; i++) {
            int sv = g_srcs[i];
            float e = g_as[sv * 4 + hd] + ad_m;
            e = (e > 0.f) ? e : 0.2f * e;
            float att = __expf(e - mx_m);
            const float* hr = g_h + (size_t)sv * 256 + lane * 8;
            float4 v0 = *(const float4*)(hr);
            float4 v1 = *(const float4*)(hr + 4);
            acc0.x = fmaf(v0.x, att, acc0.x); acc0.y = fmaf(v0.y, att, acc0.y);
            acc0.z = fmaf(v0.z, att, acc0.z); acc0.w = fmaf(v0.w, att, acc0.w);
            acc1.x = fmaf(v1.x, att, acc1.x); acc1.y = fmaf(v1.y, att, acc1.y);
            acc1.z = fmaf(v1.z, att, acc1.z); acc1.w = fmaf(v1.w, att, acc1.w);
        }
        // normalize + ELU
        acc0.x *= inv; acc0.y *= inv; acc0.z *= inv; acc0.w *= inv;
        acc1.x *= inv; acc1.y *= inv; acc1.z *= inv; acc1.w *= inv;
        acc0.x = (acc0.x > 0.f) ? acc0.x : expm1f(acc0.x);
        acc0.y = (acc0.y > 0.f) ? acc0.y : expm1f(acc0.y);
        acc0.z = (acc0.z > 0.f) ? acc0.z : expm1f(acc0.z);
        acc0.w = (acc0.w > 0.f) ? acc0.w : expm1f(acc0.w);
        acc1.x = (acc1.x > 0.f) ? acc1.x : expm1f(acc1.x);
        acc1.y = (acc1.y > 0.f) ? acc1.y : expm1f(acc1.y);
        acc1.z = (acc1.z > 0.f) ? acc1.z : expm1f(acc1.z);
        acc1.w = (acc1.w > 0.f) ? acc1.w : expm1f(acc1.w);

        float* out = g_x + (size_t)node * 256 + lane * 8;
        *(float4*)(out)     = acc0;
        *(float4*)(out + 4) = acc1;
    }
}

// ---------------- launch ----------------
extern "C" void kernel_launch(void* const* d_in, const int* in_sizes, int n_in,
                              void* d_out, int out_size) {
    const float* x  = (const float*)d_in[0];
    const int*   ei = (const int*)d_in[1];
    const int*   src = ei;
    const int*   dst = ei + NE;
    const float* W0 = (const float*)d_in[2];
    const float* a0 = (const float*)d_in[3];
    const float* W1 = (const float*)d_in[4];
    const float* a1 = (const float*)d_in[5];
    const float* W2 = (const float*)d_in[6];
    const float* a2 = (const float*)d_in[7];
    float* out = (float*)d_out;

    int node_warp_blocks = (NN + 3) / 4;   // 4 warps / 128-thread block
    int gemm_gx = (NN + 127) / 128;        // 782
    int zb = (NN * 4 + 255) / 256;

    // --- launches 0-2: weight split + alpha zero (deps for GEMM L0) ---
    wsplit_k<0><<<(128 * 256 + 255) / 256, 256>>>(W0);
    zero_asad_k<<<zb, 256>>>();
    wsplit_k<1><<<(256 * 256 + 255) / 256, 256>>>(W1);

    // --- Layer 0 GEMM + fused alpha at launch index 3 (profiled) ---
    mma_gemm_k<128><<<dim3(gemm_gx, 2), 256>>>(x, 0, IN_DIM, 0, 256, a0, 4);

    wsplit_k<2><<<(64 * 256 + 255) / 256, 256>>>(W2);

    // --- CSR by dst (counting sort) ---
    zero_k<<<(NN + 255) / 256, 256>>>();
    deg_k<<<(NE + 255) / 256, 256>>>(dst);
    scan1_k<<<NB1, SCAN_BLK>>>();
    scan2_k<<<1, 32>>>();
    scan3_k<<<(NN + 255) / 256, 256>>>();
    scatter_k<<<(NE + 255) / 256, 256>>>(src, dst);

    // --- Layer 0 edge phase ---
    attn_agg_k<4, false><<<node_warp_blocks, 128>>>(nullptr);

    // --- Layer 1 ---
    zero_asad_k<<<zb, 256>>>();
    mma_gemm_k<128><<<dim3(gemm_gx, 2), 256>>>(nullptr, 1, 256, 1, 256, a1, 4);
    attn_agg_k<4, false><<<node_warp_blocks, 128>>>(nullptr);

    // --- Layer 2 ---
    zero_asad_k<<<zb, 256>>>();
    mma_gemm_k<64><<<dim3(gemm_gx, 1), 256>>>(nullptr, 1, 256, 2, 64, a2, 1);
    attn_agg_k<1, true><<<node_warp_blocks, 128>>>(out);
}